// round 7
// baseline (speedup 1.0000x reference)
#include <cuda_runtime.h>
#include <cuda_bf16.h>

constexpr int N_NODES = 100000;
constexpr int N_EDGES = 3200000;
constexpr int F   = 32;
constexpr int L   = 50;
constexpr int EL  = 10;
constexpr int K   = 16;
constexpr int CAP = 96;   // ELL capacity (max degree ~60 for Poisson(32)); mult of 8

// Persistent scratch (static device arrays; zero-initialized at load).
// ELL slots beyond cnt[n] are NEVER written -> remain {0, 0.0f}: weight 0.0
// contributes nothing; byte-offset 0 gathers row 0 harmlessly.
// Per-layer record: { src*64 (byte offset of source row), weight bits (fp32) }.
__device__ int            g_cnt[N_NODES];
__device__ unsigned char  g_lbl8[N_NODES];
__device__ uint2          g_e0[(size_t)N_NODES * CAP];    // layer-1 records
__device__ uint2          g_e1[(size_t)N_NODES * CAP];    // layer-2 records
__device__ uint2          g_e2[(size_t)N_NODES * CAP];    // layer-3 records
__device__ unsigned       g_xb[(size_t)N_NODES * (F / 2)]; // bf16x2 rows (64B/row)
__device__ unsigned       g_hA[(size_t)N_NODES * (F / 2)];
__device__ unsigned       g_hB[(size_t)N_NODES * (F / 2)];
__device__ float          g_sums[L * F];                   // zeroed by final_head

// ---------------------------------------------------------------------------
__global__ __launch_bounds__(256)
void prep_nodes(const int* __restrict__ lbl)
{
    int i = blockIdx.x * blockDim.x + threadIdx.x;
    if (i < N_NODES) {
        g_lbl8[i] = (unsigned char)lbl[i];
        g_cnt[i]  = 0;
    }
}

__global__ __launch_bounds__(256)
void x_to_bf16(const float* __restrict__ x)
{
    int i = blockIdx.x * blockDim.x + threadIdx.x;   // over N*F/2
    if (i < N_NODES * (F / 2)) {
        __nv_bfloat162 h2 = __floats2bfloat162_rn(x[2 * i], x[2 * i + 1]);
        g_xb[i] = *reinterpret_cast<unsigned*>(&h2);
    }
}

// ---------------------------------------------------------------------------
// build ELL: per-layer {offset, weight} records
// ---------------------------------------------------------------------------
__global__ __launch_bounds__(256)
void build_ell(const int* __restrict__ esrc,
               const int* __restrict__ edst,
               const int* __restrict__ elab,
               const float* __restrict__ W1,
               const float* __restrict__ W2,
               const float* __restrict__ W3)
{
    int e = blockIdx.x * blockDim.x + threadIdx.x;
    if (e >= N_EDGES) return;
    int s = esrc[e];
    int d = edst[e];
    unsigned ls = g_lbl8[s];
    unsigned ld = g_lbl8[d];
    unsigned widx = (ls * L + ld) * EL + (unsigned)elab[e];
    int pos = atomicAdd(&g_cnt[d], 1);
    size_t slot = (size_t)d * CAP + pos;
    unsigned off = (unsigned)s * 64u;
    g_e0[slot] = make_uint2(off, __float_as_uint(__ldg(&W1[widx])));
    g_e1[slot] = make_uint2(off, __float_as_uint(__ldg(&W2[widx])));
    g_e2[slot] = make_uint2(off, __float_as_uint(__ldg(&W3[widx])));
}

// ---------------------------------------------------------------------------
// Node accumulation: 8 edges per warp iteration. lane = 8*g + c;
// group g handles edges (j+2g, j+2g+1) -> one uint4 = two records.
// Returns per-lane partial float4 (features [4c,4c+4)), reduced over g later.
// ---------------------------------------------------------------------------
__device__ __forceinline__
float4 node_acc4(const unsigned* __restrict__ x_in,
                 const uint2*    __restrict__ edata,
                 int cnt, int g, int c)
{
    const char* xb = (const char*)x_in + c * 8;   // per-lane base
    float4 acc = make_float4(0.f, 0.f, 0.f, 0.f);
    int cnt_r = (cnt + 7) & ~7;                   // padded slots are zero-weight
    const uint4* ed4 = reinterpret_cast<const uint4*>(edata);
    for (int j = 0; j < cnt_r; j += 8) {
        uint4 rr = __ldg(&ed4[(j >> 1) + g]);     // records j+2g, j+2g+1
        float w0 = __uint_as_float(rr.y);
        float w1 = __uint_as_float(rr.w);
        uint2 a0 = __ldg(reinterpret_cast<const uint2*>(xb + rr.x));
        uint2 a1 = __ldg(reinterpret_cast<const uint2*>(xb + rr.z));
        acc.x = fmaf(w0, __uint_as_float(a0.x << 16),         acc.x);
        acc.y = fmaf(w0, __uint_as_float(a0.x & 0xFFFF0000u), acc.y);
        acc.z = fmaf(w0, __uint_as_float(a0.y << 16),         acc.z);
        acc.w = fmaf(w0, __uint_as_float(a0.y & 0xFFFF0000u), acc.w);
        acc.x = fmaf(w1, __uint_as_float(a1.x << 16),         acc.x);
        acc.y = fmaf(w1, __uint_as_float(a1.x & 0xFFFF0000u), acc.y);
        acc.z = fmaf(w1, __uint_as_float(a1.y << 16),         acc.z);
        acc.w = fmaf(w1, __uint_as_float(a1.y & 0xFFFF0000u), acc.w);
    }
    return acc;
}

__device__ __forceinline__
float4 reduce_groups(float4 a)
{
    #pragma unroll
    for (int m = 8; m <= 16; m <<= 1) {
        a.x += __shfl_xor_sync(0xffffffffu, a.x, m);
        a.y += __shfl_xor_sync(0xffffffffu, a.y, m);
        a.z += __shfl_xor_sync(0xffffffffu, a.z, m);
        a.w += __shfl_xor_sync(0xffffffffu, a.w, m);
    }
    return a;
}

// ---------------------------------------------------------------------------
// conv layers 1,2
// ---------------------------------------------------------------------------
__global__ __launch_bounds__(256)
void conv_ell(const unsigned* __restrict__ x_in,
              unsigned*       __restrict__ h_out,
              const uint2*    __restrict__ erec,
              const float* __restrict__ b)
{
    int n    = (blockIdx.x * blockDim.x + threadIdx.x) >> 5;
    int lane = threadIdx.x & 31;
    if (n >= N_NODES) return;
    int g = lane >> 3, c = lane & 7;

    int cnt = __ldg(&g_cnt[n]);
    float4 acc = node_acc4(x_in, &erec[(size_t)n * CAP], cnt, g, c);
    acc = reduce_groups(acc);

    if (g == 0) {
        float bias = b[g_lbl8[n]];
        __nv_bfloat162 p0 = __floats2bfloat162_rn(tanhf(acc.x + bias), tanhf(acc.y + bias));
        __nv_bfloat162 p1 = __floats2bfloat162_rn(tanhf(acc.z + bias), tanhf(acc.w + bias));
        uint2 st;
        st.x = *reinterpret_cast<unsigned*>(&p0);
        st.y = *reinterpret_cast<unsigned*>(&p1);
        reinterpret_cast<uint2*>(h_out)[(size_t)n * 8 + c] = st;
    }
}

// ---------------------------------------------------------------------------
// conv layer 3 fused with label pooling
// ---------------------------------------------------------------------------
__global__ __launch_bounds__(256)
void conv_ell_pool(const unsigned* __restrict__ x_in,
                   const uint2*    __restrict__ erec,
                   const float* __restrict__ b)
{
    __shared__ float pool[L * F];
    for (int i = threadIdx.x; i < L * F; i += blockDim.x) pool[i] = 0.0f;
    __syncthreads();

    int lane = threadIdx.x & 31;
    int g = lane >> 3, c = lane & 7;
    int wpb = blockDim.x >> 5;
    int n0  = blockIdx.x * wpb + (threadIdx.x >> 5);
    int ns  = gridDim.x * wpb;

    for (int n = n0; n < N_NODES; n += ns) {
        int cnt = __ldg(&g_cnt[n]);
        float4 acc = node_acc4(x_in, &erec[(size_t)n * CAP], cnt, g, c);
        acc = reduce_groups(acc);
        if (g == 0) {
            int   l    = g_lbl8[n];
            float bias = b[l];
            atomicAdd(&pool[l * F + 4 * c + 0], tanhf(acc.x + bias));
            atomicAdd(&pool[l * F + 4 * c + 1], tanhf(acc.y + bias));
            atomicAdd(&pool[l * F + 4 * c + 2], tanhf(acc.z + bias));
            atomicAdd(&pool[l * F + 4 * c + 3], tanhf(acc.w + bias));
        }
    }
    __syncthreads();

    for (int i = threadIdx.x; i < L * F; i += blockDim.x)
        atomicAdd(&g_sums[i], pool[i]);
}

// ---------------------------------------------------------------------------
__global__ __launch_bounds__(512)
void final_head(const float* __restrict__ Wr,
                const float* __restrict__ br,
                float* __restrict__ out)
{
    __shared__ float red[512];
    int t = threadIdx.x;
    int k = t & 15;
    int chunk = t >> 4;

    float acc = 0.0f;
    for (int i = chunk; i < L * F; i += 32)
        acc += g_sums[i] * Wr[i * K + k];
    red[t] = acc;
    __syncthreads();

    #pragma unroll
    for (int s = 256; s >= 16; s >>= 1) {
        if (t < s) red[t] += red[t + s];
        __syncthreads();
    }
    if (t < K) out[t] = tanhf(red[t] + br[t]);
    __syncthreads();

    for (int i = t; i < L * F; i += 512) g_sums[i] = 0.0f;   // reset invariant
}

// ---------------------------------------------------------------------------
// inputs: 0:x 1:W1 2:b1 3:W2 4:b2 5:W3 6:b3 7:Wr 8:br 9:node_labels
//         10:edge_src 11:edge_dst 12:edge_labels
// ---------------------------------------------------------------------------
extern "C" void kernel_launch(void* const* d_in, const int* in_sizes, int n_in,
                              void* d_out, int out_size)
{
    const float* x   = (const float*)d_in[0];
    const float* W1  = (const float*)d_in[1];
    const float* b1  = (const float*)d_in[2];
    const float* W2  = (const float*)d_in[3];
    const float* b2  = (const float*)d_in[4];
    const float* W3  = (const float*)d_in[5];
    const float* b3  = (const float*)d_in[6];
    const float* Wr  = (const float*)d_in[7];
    const float* br  = (const float*)d_in[8];
    const int* lbl   = (const int*)d_in[9];
    const int* esrc  = (const int*)d_in[10];
    const int* edst  = (const int*)d_in[11];
    const int* elab  = (const int*)d_in[12];
    float* out = (float*)d_out;

    unsigned *xb, *hA, *hB;
    uint2 *e0, *e1, *e2;
    cudaGetSymbolAddress((void**)&xb, g_xb);
    cudaGetSymbolAddress((void**)&hA, g_hA);
    cudaGetSymbolAddress((void**)&hB, g_hB);
    cudaGetSymbolAddress((void**)&e0, g_e0);
    cudaGetSymbolAddress((void**)&e1, g_e1);
    cudaGetSymbolAddress((void**)&e2, g_e2);

    const int ng = (N_NODES + 255) / 256;            // 391
    const int pg = (N_NODES * (F / 2) + 255) / 256;  // 6250
    const int eg = (N_EDGES + 255) / 256;            // 12500
    const int cg = (N_NODES * 32 + 255) / 256;       // warp per node

    prep_nodes<<<ng, 256>>>(lbl);
    x_to_bf16<<<pg, 256>>>(x);
    build_ell<<<eg, 256>>>(esrc, edst, elab, W1, W2, W3);

    conv_ell<<<cg, 256>>>(xb, hA, e0, b1);
    conv_ell<<<cg, 256>>>(hA, hB, e1, b2);
    conv_ell_pool<<<1184, 256>>>(hB, e2, b3);

    final_head<<<1, 512>>>(Wr, br, out);
}

// round 8
// speedup vs baseline: 1.5739x; 1.5739x over previous
#include <cuda_runtime.h>
#include <cuda_bf16.h>

constexpr int N_NODES = 100000;
constexpr int N_EDGES = 3200000;
constexpr int F   = 32;
constexpr int L   = 50;
constexpr int EL  = 10;
constexpr int K   = 16;
constexpr int CAP = 96;       // ELL capacity (max degree ~60); multiple of 8
constexpr int NW  = L * L * EL;   // 25000 weight entries

// Persistent scratch (static device arrays; zero-initialized at load).
// ELL slots beyond cnt[n] are NEVER written -> stay 0 -> weight-index field 0
// -> Wp[0] == 0.0f contributes nothing; src field 0 gathers row 0 harmlessly.
__device__ int            g_cnt[N_NODES];
__device__ unsigned char  g_lbl8[N_NODES];
__device__ unsigned       g_edata[(size_t)N_NODES * CAP];  // src(17b) | (widx+1)<<17
__device__ float          g_Wp0[NW + 1];                   // padded weights, [0]=0
__device__ float          g_Wp1[NW + 1];
__device__ float          g_Wp2[NW + 1];
__device__ unsigned       g_xb[(size_t)N_NODES * (F / 2)]; // bf16x2 rows (64B/row)
__device__ unsigned       g_hA[(size_t)N_NODES * (F / 2)];
__device__ unsigned       g_hB[(size_t)N_NODES * (F / 2)];
__device__ float          g_sums[L * F];                   // zeroed by final_head

// ---------------------------------------------------------------------------
__global__ __launch_bounds__(256)
void prep_nodes(const int* __restrict__ lbl)
{
    int i = blockIdx.x * blockDim.x + threadIdx.x;
    if (i < N_NODES) {
        g_lbl8[i] = (unsigned char)lbl[i];
        g_cnt[i]  = 0;
    }
}

__global__ __launch_bounds__(256)
void pad_w(const float* __restrict__ W1,
           const float* __restrict__ W2,
           const float* __restrict__ W3)
{
    int i = blockIdx.x * blockDim.x + threadIdx.x;
    if (i <= NW) {
        g_Wp0[i] = (i == 0) ? 0.0f : W1[i - 1];
        g_Wp1[i] = (i == 0) ? 0.0f : W2[i - 1];
        g_Wp2[i] = (i == 0) ? 0.0f : W3[i - 1];
    }
}

__global__ __launch_bounds__(256)
void x_to_bf16(const float* __restrict__ x)
{
    int i = blockIdx.x * blockDim.x + threadIdx.x;   // over N*F/2
    if (i < N_NODES * (F / 2)) {
        __nv_bfloat162 h2 = __floats2bfloat162_rn(x[2 * i], x[2 * i + 1]);
        g_xb[i] = *reinterpret_cast<unsigned*>(&h2);
    }
}

// ---------------------------------------------------------------------------
__global__ __launch_bounds__(256)
void build_ell(const int* __restrict__ esrc,
               const int* __restrict__ edst,
               const int* __restrict__ elab)
{
    int e = blockIdx.x * blockDim.x + threadIdx.x;
    if (e >= N_EDGES) return;
    int s = esrc[e];
    int d = edst[e];
    unsigned ls = g_lbl8[s];
    unsigned ld = g_lbl8[d];
    unsigned widx = (ls * L + ld) * EL + (unsigned)elab[e] + 1u;  // 1..25000
    int pos = atomicAdd(&g_cnt[d], 1);
    g_edata[(size_t)d * CAP + pos] = (unsigned)s | (widx << 17);
}

// ---------------------------------------------------------------------------
// Node accumulation: 8 edges per iteration, lane = 8*g + c.
// Group g handles edges (j+2g, j+2g+1): one LDG.64 fetches both records.
// No tail predication: padded slots have weight-index 0 -> Wp[0] = 0.
// ---------------------------------------------------------------------------
__device__ __forceinline__
float4 node_acc(const unsigned* __restrict__ x_in,
                const float*    __restrict__ Wp,
                const unsigned* __restrict__ edata,
                int cnt, int g, int c)
{
    const char* xb = (const char*)x_in + c * 8;   // per-lane feature base
    const uint2* ed2 = reinterpret_cast<const uint2*>(edata);
    float4 acc = make_float4(0.f, 0.f, 0.f, 0.f);
    int cnt_r = (cnt + 7) & ~7;
    #pragma unroll 2
    for (int j = 0; j < cnt_r; j += 8) {
        uint2 rr = __ldg(&ed2[(j >> 1) + g]);     // records j+2g, j+2g+1
        float w0 = __ldg(&Wp[rr.x >> 17]);
        float w1 = __ldg(&Wp[rr.y >> 17]);
        uint2 a0 = __ldg(reinterpret_cast<const uint2*>(xb + (size_t)(rr.x & 0x1FFFFu) * 64u));
        uint2 a1 = __ldg(reinterpret_cast<const uint2*>(xb + (size_t)(rr.y & 0x1FFFFu) * 64u));
        acc.x = fmaf(w0, __uint_as_float(a0.x << 16),         acc.x);
        acc.y = fmaf(w0, __uint_as_float(a0.x & 0xFFFF0000u), acc.y);
        acc.z = fmaf(w0, __uint_as_float(a0.y << 16),         acc.z);
        acc.w = fmaf(w0, __uint_as_float(a0.y & 0xFFFF0000u), acc.w);
        acc.x = fmaf(w1, __uint_as_float(a1.x << 16),         acc.x);
        acc.y = fmaf(w1, __uint_as_float(a1.x & 0xFFFF0000u), acc.y);
        acc.z = fmaf(w1, __uint_as_float(a1.y << 16),         acc.z);
        acc.w = fmaf(w1, __uint_as_float(a1.y & 0xFFFF0000u), acc.w);
    }
    return acc;
}

__device__ __forceinline__
float4 reduce_groups(float4 a)
{
    #pragma unroll
    for (int m = 8; m <= 16; m <<= 1) {
        a.x += __shfl_xor_sync(0xffffffffu, a.x, m);
        a.y += __shfl_xor_sync(0xffffffffu, a.y, m);
        a.z += __shfl_xor_sync(0xffffffffu, a.z, m);
        a.w += __shfl_xor_sync(0xffffffffu, a.w, m);
    }
    return a;
}

// ---------------------------------------------------------------------------
// conv layers 1,2
// ---------------------------------------------------------------------------
__global__ __launch_bounds__(256)
void conv_ell(const unsigned* __restrict__ x_in,
              unsigned*       __restrict__ h_out,
              const float*    __restrict__ Wp,
              const float*    __restrict__ b)
{
    int n    = (blockIdx.x * blockDim.x + threadIdx.x) >> 5;
    int lane = threadIdx.x & 31;
    if (n >= N_NODES) return;
    int g = lane >> 3, c = lane & 7;

    int cnt = __ldg(&g_cnt[n]);
    float4 acc = node_acc(x_in, Wp, &g_edata[(size_t)n * CAP], cnt, g, c);
    acc = reduce_groups(acc);

    if (g == 0) {
        float bias = b[g_lbl8[n]];
        __nv_bfloat162 p0 = __floats2bfloat162_rn(tanhf(acc.x + bias), tanhf(acc.y + bias));
        __nv_bfloat162 p1 = __floats2bfloat162_rn(tanhf(acc.z + bias), tanhf(acc.w + bias));
        uint2 st;
        st.x = *reinterpret_cast<unsigned*>(&p0);
        st.y = *reinterpret_cast<unsigned*>(&p1);
        reinterpret_cast<uint2*>(h_out)[(size_t)n * 8 + c] = st;
    }
}

// ---------------------------------------------------------------------------
// conv layer 3 fused with label pooling
// ---------------------------------------------------------------------------
__global__ __launch_bounds__(256)
void conv_ell_pool(const unsigned* __restrict__ x_in,
                   const float*    __restrict__ Wp,
                   const float*    __restrict__ b)
{
    __shared__ float pool[L * F];
    for (int i = threadIdx.x; i < L * F; i += blockDim.x) pool[i] = 0.0f;
    __syncthreads();

    int lane = threadIdx.x & 31;
    int g = lane >> 3, c = lane & 7;
    int wpb = blockDim.x >> 5;
    int n0  = blockIdx.x * wpb + (threadIdx.x >> 5);
    int ns  = gridDim.x * wpb;

    for (int n = n0; n < N_NODES; n += ns) {
        int cnt = __ldg(&g_cnt[n]);
        float4 acc = node_acc(x_in, Wp, &g_edata[(size_t)n * CAP], cnt, g, c);
        acc = reduce_groups(acc);
        if (g == 0) {
            int   l    = g_lbl8[n];
            float bias = b[l];
            atomicAdd(&pool[l * F + 4 * c + 0], tanhf(acc.x + bias));
            atomicAdd(&pool[l * F + 4 * c + 1], tanhf(acc.y + bias));
            atomicAdd(&pool[l * F + 4 * c + 2], tanhf(acc.z + bias));
            atomicAdd(&pool[l * F + 4 * c + 3], tanhf(acc.w + bias));
        }
    }
    __syncthreads();

    for (int i = threadIdx.x; i < L * F; i += blockDim.x)
        atomicAdd(&g_sums[i], pool[i]);
}

// ---------------------------------------------------------------------------
__global__ __launch_bounds__(512)
void final_head(const float* __restrict__ Wr,
                const float* __restrict__ br,
                float* __restrict__ out)
{
    __shared__ float red[512];
    int t = threadIdx.x;
    int k = t & 15;
    int chunk = t >> 4;

    float acc = 0.0f;
    for (int i = chunk; i < L * F; i += 32)
        acc += g_sums[i] * Wr[i * K + k];
    red[t] = acc;
    __syncthreads();

    #pragma unroll
    for (int s = 256; s >= 16; s >>= 1) {
        if (t < s) red[t] += red[t + s];
        __syncthreads();
    }
    if (t < K) out[t] = tanhf(red[t] + br[t]);
    __syncthreads();

    for (int i = t; i < L * F; i += 512) g_sums[i] = 0.0f;   // reset invariant
}

// ---------------------------------------------------------------------------
// inputs: 0:x 1:W1 2:b1 3:W2 4:b2 5:W3 6:b3 7:Wr 8:br 9:node_labels
//         10:edge_src 11:edge_dst 12:edge_labels
// ---------------------------------------------------------------------------
extern "C" void kernel_launch(void* const* d_in, const int* in_sizes, int n_in,
                              void* d_out, int out_size)
{
    const float* x   = (const float*)d_in[0];
    const float* W1  = (const float*)d_in[1];
    const float* b1  = (const float*)d_in[2];
    const float* W2  = (const float*)d_in[3];
    const float* b2  = (const float*)d_in[4];
    const float* W3  = (const float*)d_in[5];
    const float* b3  = (const float*)d_in[6];
    const float* Wr  = (const float*)d_in[7];
    const float* br  = (const float*)d_in[8];
    const int* lbl   = (const int*)d_in[9];
    const int* esrc  = (const int*)d_in[10];
    const int* edst  = (const int*)d_in[11];
    const int* elab  = (const int*)d_in[12];
    float* out = (float*)d_out;

    unsigned *xb, *hA, *hB;
    float *wp0, *wp1, *wp2;
    cudaGetSymbolAddress((void**)&xb,  g_xb);
    cudaGetSymbolAddress((void**)&hA,  g_hA);
    cudaGetSymbolAddress((void**)&hB,  g_hB);
    cudaGetSymbolAddress((void**)&wp0, g_Wp0);
    cudaGetSymbolAddress((void**)&wp1, g_Wp1);
    cudaGetSymbolAddress((void**)&wp2, g_Wp2);

    const int ng = (N_NODES + 255) / 256;            // 391
    const int pg = (N_NODES * (F / 2) + 255) / 256;  // 6250
    const int eg = (N_EDGES + 255) / 256;            // 12500
    const int wg = (NW + 1 + 255) / 256;             // 98
    const int cg = (N_NODES * 32 + 255) / 256;       // warp per node

    prep_nodes<<<ng, 256>>>(lbl);
    pad_w<<<wg, 256>>>(W1, W2, W3);
    x_to_bf16<<<pg, 256>>>(x);
    build_ell<<<eg, 256>>>(esrc, edst, elab);

    conv_ell<<<cg, 256>>>(xb, hA, wp0, b1);
    conv_ell<<<cg, 256>>>(hA, hB, wp1, b2);
    conv_ell_pool<<<1184, 256>>>(hB, wp2, b3);

    final_head<<<1, 512>>>(Wr, br, out);
}

// round 9
// speedup vs baseline: 1.6088x; 1.0222x over previous
#include <cuda_runtime.h>
#include <cuda_bf16.h>

constexpr int N_NODES = 100000;
constexpr int N_EDGES = 3200000;
constexpr int F   = 32;
constexpr int L   = 50;
constexpr int EL  = 10;
constexpr int K   = 16;
constexpr int CAP = 96;          // ELL capacity (max degree ~60); multiple of 8
constexpr int NW  = L * L * EL;  // 25000 weight entries

// Persistent scratch (static device arrays; zero-initialized at load).
// ELL slots beyond cnt[n] are NEVER written -> stay 0 -> weight-index field 0
// -> Wp[0] == 0.0f contributes nothing; src field 0 gathers row 0 harmlessly.
__device__ int            g_cnt[N_NODES];
__device__ unsigned char  g_lbl8[N_NODES];
__device__ unsigned       g_edata[(size_t)N_NODES * CAP];  // src(17b) | (widx+1)<<17
__device__ float          g_Wp0[NW + 1];                   // padded weights, [0]=0
__device__ float          g_Wp1[NW + 1];
__device__ float          g_Wp2[NW + 1];
__device__ unsigned       g_xb[(size_t)N_NODES * (F / 2)]; // bf16x2 rows (64B/row)
__device__ unsigned       g_hA[(size_t)N_NODES * (F / 2)];
__device__ unsigned       g_hB[(size_t)N_NODES * (F / 2)];
__device__ float          g_sums[L * F];                   // zeroed by final_head

// ---------------------------------------------------------------------------
// fused prep: pack x to bf16x2 (1.6M items), compact labels + zero cnt (100K),
// build padded weight tables (25K). One launch.
// ---------------------------------------------------------------------------
__global__ __launch_bounds__(256)
void prep_all(const float* __restrict__ x,
              const int*   __restrict__ lbl,
              const float* __restrict__ W1,
              const float* __restrict__ W2,
              const float* __restrict__ W3)
{
    int i = blockIdx.x * blockDim.x + threadIdx.x;
    if (i < N_NODES * (F / 2)) {
        __nv_bfloat162 h2 = __floats2bfloat162_rn(x[2 * i], x[2 * i + 1]);
        g_xb[i] = *reinterpret_cast<unsigned*>(&h2);
    }
    if (i < N_NODES) {
        g_lbl8[i] = (unsigned char)lbl[i];
        g_cnt[i]  = 0;
    }
    if (i <= NW) {
        g_Wp0[i] = (i == 0) ? 0.0f : W1[i - 1];
        g_Wp1[i] = (i == 0) ? 0.0f : W2[i - 1];
        g_Wp2[i] = (i == 0) ? 0.0f : W3[i - 1];
    }
}

// ---------------------------------------------------------------------------
// build ELL: 4 edges per thread for MLP on the atomic path.
// ---------------------------------------------------------------------------
__global__ __launch_bounds__(256)
void build_ell4(const int4* __restrict__ esrc4,
                const int4* __restrict__ edst4,
                const int4* __restrict__ elab4)
{
    int t = blockIdx.x * blockDim.x + threadIdx.x;
    if (t >= N_EDGES / 4) return;
    int4 s = __ldg(&esrc4[t]);
    int4 d = __ldg(&edst4[t]);
    int4 l = __ldg(&elab4[t]);

    unsigned w0 = ((unsigned)g_lbl8[s.x] * L + g_lbl8[d.x]) * EL + (unsigned)l.x + 1u;
    unsigned w1 = ((unsigned)g_lbl8[s.y] * L + g_lbl8[d.y]) * EL + (unsigned)l.y + 1u;
    unsigned w2 = ((unsigned)g_lbl8[s.z] * L + g_lbl8[d.z]) * EL + (unsigned)l.z + 1u;
    unsigned w3 = ((unsigned)g_lbl8[s.w] * L + g_lbl8[d.w]) * EL + (unsigned)l.w + 1u;

    int p0 = atomicAdd(&g_cnt[d.x], 1);
    int p1 = atomicAdd(&g_cnt[d.y], 1);
    int p2 = atomicAdd(&g_cnt[d.z], 1);
    int p3 = atomicAdd(&g_cnt[d.w], 1);

    g_edata[(size_t)d.x * CAP + p0] = (unsigned)s.x | (w0 << 17);
    g_edata[(size_t)d.y * CAP + p1] = (unsigned)s.y | (w1 << 17);
    g_edata[(size_t)d.z * CAP + p2] = (unsigned)s.z | (w2 << 17);
    g_edata[(size_t)d.w * CAP + p3] = (unsigned)s.w | (w3 << 17);
}

// ---------------------------------------------------------------------------
// Node accumulation: 8 edges per iteration, lane = 8*g + c.
// Group g handles edges (j+2g, j+2g+1): one LDG.64 fetches both records.
// No tail predication: padded slots have weight-index 0 -> Wp[0] = 0.
// ---------------------------------------------------------------------------
__device__ __forceinline__
float4 node_acc(const unsigned* __restrict__ x_in,
                const float*    __restrict__ Wp,
                const unsigned* __restrict__ edata,
                int cnt, int g, int c)
{
    const char* xb = (const char*)x_in + c * 8;
    const uint2* ed2 = reinterpret_cast<const uint2*>(edata);
    float4 acc = make_float4(0.f, 0.f, 0.f, 0.f);
    int cnt_r = (cnt + 7) & ~7;
    #pragma unroll 2
    for (int j = 0; j < cnt_r; j += 8) {
        uint2 rr = __ldg(&ed2[(j >> 1) + g]);
        float w0 = __ldg(&Wp[rr.x >> 17]);
        float w1 = __ldg(&Wp[rr.y >> 17]);
        uint2 a0 = __ldg(reinterpret_cast<const uint2*>(xb + (size_t)(rr.x & 0x1FFFFu) * 64u));
        uint2 a1 = __ldg(reinterpret_cast<const uint2*>(xb + (size_t)(rr.y & 0x1FFFFu) * 64u));
        acc.x = fmaf(w0, __uint_as_float(a0.x << 16),         acc.x);
        acc.y = fmaf(w0, __uint_as_float(a0.x & 0xFFFF0000u), acc.y);
        acc.z = fmaf(w0, __uint_as_float(a0.y << 16),         acc.z);
        acc.w = fmaf(w0, __uint_as_float(a0.y & 0xFFFF0000u), acc.w);
        acc.x = fmaf(w1, __uint_as_float(a1.x << 16),         acc.x);
        acc.y = fmaf(w1, __uint_as_float(a1.x & 0xFFFF0000u), acc.y);
        acc.z = fmaf(w1, __uint_as_float(a1.y << 16),         acc.z);
        acc.w = fmaf(w1, __uint_as_float(a1.y & 0xFFFF0000u), acc.w);
    }
    return acc;
}

__device__ __forceinline__
float4 reduce_groups(float4 a)
{
    #pragma unroll
    for (int m = 8; m <= 16; m <<= 1) {
        a.x += __shfl_xor_sync(0xffffffffu, a.x, m);
        a.y += __shfl_xor_sync(0xffffffffu, a.y, m);
        a.z += __shfl_xor_sync(0xffffffffu, a.z, m);
        a.w += __shfl_xor_sync(0xffffffffu, a.w, m);
    }
    return a;
}

// ---------------------------------------------------------------------------
__global__ __launch_bounds__(256)
void conv_ell(const unsigned* __restrict__ x_in,
              unsigned*       __restrict__ h_out,
              const float*    __restrict__ Wp,
              const float*    __restrict__ b)
{
    int n    = (blockIdx.x * blockDim.x + threadIdx.x) >> 5;
    int lane = threadIdx.x & 31;
    if (n >= N_NODES) return;
    int g = lane >> 3, c = lane & 7;

    int cnt = __ldg(&g_cnt[n]);
    float4 acc = node_acc(x_in, Wp, &g_edata[(size_t)n * CAP], cnt, g, c);
    acc = reduce_groups(acc);

    if (g == 0) {
        float bias = b[g_lbl8[n]];
        __nv_bfloat162 p0 = __floats2bfloat162_rn(tanhf(acc.x + bias), tanhf(acc.y + bias));
        __nv_bfloat162 p1 = __floats2bfloat162_rn(tanhf(acc.z + bias), tanhf(acc.w + bias));
        uint2 st;
        st.x = *reinterpret_cast<unsigned*>(&p0);
        st.y = *reinterpret_cast<unsigned*>(&p1);
        reinterpret_cast<uint2*>(h_out)[(size_t)n * 8 + c] = st;
    }
}

// ---------------------------------------------------------------------------
__global__ __launch_bounds__(256)
void conv_ell_pool(const unsigned* __restrict__ x_in,
                   const float*    __restrict__ Wp,
                   const float*    __restrict__ b)
{
    __shared__ float pool[L * F];
    for (int i = threadIdx.x; i < L * F; i += blockDim.x) pool[i] = 0.0f;
    __syncthreads();

    int lane = threadIdx.x & 31;
    int g = lane >> 3, c = lane & 7;
    int wpb = blockDim.x >> 5;
    int n0  = blockIdx.x * wpb + (threadIdx.x >> 5);
    int ns  = gridDim.x * wpb;

    for (int n = n0; n < N_NODES; n += ns) {
        int cnt = __ldg(&g_cnt[n]);
        float4 acc = node_acc(x_in, Wp, &g_edata[(size_t)n * CAP], cnt, g, c);
        acc = reduce_groups(acc);
        if (g == 0) {
            int   l    = g_lbl8[n];
            float bias = b[l];
            atomicAdd(&pool[l * F + 4 * c + 0], tanhf(acc.x + bias));
            atomicAdd(&pool[l * F + 4 * c + 1], tanhf(acc.y + bias));
            atomicAdd(&pool[l * F + 4 * c + 2], tanhf(acc.z + bias));
            atomicAdd(&pool[l * F + 4 * c + 3], tanhf(acc.w + bias));
        }
    }
    __syncthreads();

    for (int i = threadIdx.x; i < L * F; i += blockDim.x)
        atomicAdd(&g_sums[i], pool[i]);
}

// ---------------------------------------------------------------------------
__global__ __launch_bounds__(512)
void final_head(const float* __restrict__ Wr,
                const float* __restrict__ br,
                float* __restrict__ out)
{
    __shared__ float red[512];
    int t = threadIdx.x;
    int k = t & 15;
    int chunk = t >> 4;

    float acc = 0.0f;
    for (int i = chunk; i < L * F; i += 32)
        acc += g_sums[i] * Wr[i * K + k];
    red[t] = acc;
    __syncthreads();

    #pragma unroll
    for (int s = 256; s >= 16; s >>= 1) {
        if (t < s) red[t] += red[t + s];
        __syncthreads();
    }
    if (t < K) out[t] = tanhf(red[t] + br[t]);
    __syncthreads();

    for (int i = t; i < L * F; i += 512) g_sums[i] = 0.0f;   // reset invariant
}

// ---------------------------------------------------------------------------
// inputs: 0:x 1:W1 2:b1 3:W2 4:b2 5:W3 6:b3 7:Wr 8:br 9:node_labels
//         10:edge_src 11:edge_dst 12:edge_labels
// ---------------------------------------------------------------------------
extern "C" void kernel_launch(void* const* d_in, const int* in_sizes, int n_in,
                              void* d_out, int out_size)
{
    const float* x   = (const float*)d_in[0];
    const float* W1  = (const float*)d_in[1];
    const float* b1  = (const float*)d_in[2];
    const float* W2  = (const float*)d_in[3];
    const float* b2  = (const float*)d_in[4];
    const float* W3  = (const float*)d_in[5];
    const float* b3  = (const float*)d_in[6];
    const float* Wr  = (const float*)d_in[7];
    const float* br  = (const float*)d_in[8];
    const int* lbl   = (const int*)d_in[9];
    const int* esrc  = (const int*)d_in[10];
    const int* edst  = (const int*)d_in[11];
    const int* elab  = (const int*)d_in[12];
    float* out = (float*)d_out;

    unsigned *xb, *hA, *hB;
    float *wp0, *wp1, *wp2;
    cudaGetSymbolAddress((void**)&xb,  g_xb);
    cudaGetSymbolAddress((void**)&hA,  g_hA);
    cudaGetSymbolAddress((void**)&hB,  g_hB);
    cudaGetSymbolAddress((void**)&wp0, g_Wp0);
    cudaGetSymbolAddress((void**)&wp1, g_Wp1);
    cudaGetSymbolAddress((void**)&wp2, g_Wp2);

    const int pg = (N_NODES * (F / 2) + 255) / 256;  // 6250 (covers all prep work)
    const int bg = (N_EDGES / 4 + 255) / 256;        // 3125
    const int cg = (N_NODES * 32 + 255) / 256;       // warp per node

    prep_all<<<pg, 256>>>(x, lbl, W1, W2, W3);
    build_ell4<<<bg, 256>>>((const int4*)esrc, (const int4*)edst, (const int4*)elab);

    conv_ell<<<cg, 256>>>(xb, hA, wp0, b1);
    conv_ell<<<cg, 256>>>(hA, hB, wp1, b2);
    conv_ell_pool<<<1184, 256>>>(hB, wp2, b3);

    final_head<<<1, 512>>>(Wr, br, out);
}

// round 10
// speedup vs baseline: 1.6429x; 1.0212x over previous
#include <cuda_runtime.h>
#include <cuda_bf16.h>

constexpr int N_NODES = 100000;
constexpr int N_EDGES = 3200000;
constexpr int F   = 32;
constexpr int L   = 50;
constexpr int EL  = 10;
constexpr int K   = 16;
constexpr int CAP = 96;          // ELL capacity (max degree ~60); multiple of 8
constexpr int NW  = L * L * EL;  // 25000 weight entries

// Persistent scratch (static device arrays; zero-initialized at load).
// ELL slots beyond cnt[n] are NEVER written -> stay 0 -> weight-index field 0
// -> Wp[0] == 0.0f contributes nothing; src field 0 gathers row 0 harmlessly.
__device__ int            g_cnt[N_NODES];
__device__ unsigned char  g_lbl8[N_NODES];
__device__ unsigned       g_edata[(size_t)N_NODES * CAP];  // src(17b) | (widx+1)<<17
__device__ float          g_Wp0[NW + 1];                   // padded weights, [0]=0
__device__ float          g_Wp1[NW + 1];
__device__ float          g_Wp2[NW + 1];
__device__ float          g_hA[(size_t)N_NODES * F];       // fp32 h buffers
__device__ float          g_hB[(size_t)N_NODES * F];
__device__ float          g_sums[L * F];                   // zeroed by final_head

// ---------------------------------------------------------------------------
// prep: compact labels + zero cnt (100K), padded weight tables (25K).
// ---------------------------------------------------------------------------
__global__ __launch_bounds__(256)
void prep_all(const int*   __restrict__ lbl,
              const float* __restrict__ W1,
              const float* __restrict__ W2,
              const float* __restrict__ W3)
{
    int i = blockIdx.x * blockDim.x + threadIdx.x;
    if (i < N_NODES) {
        g_lbl8[i] = (unsigned char)lbl[i];
        g_cnt[i]  = 0;
    }
    if (i <= NW) {
        g_Wp0[i] = (i == 0) ? 0.0f : W1[i - 1];
        g_Wp1[i] = (i == 0) ? 0.0f : W2[i - 1];
        g_Wp2[i] = (i == 0) ? 0.0f : W3[i - 1];
    }
}

// ---------------------------------------------------------------------------
// build ELL: 4 edges per thread for MLP on the atomic path.
// ---------------------------------------------------------------------------
__global__ __launch_bounds__(256)
void build_ell4(const int4* __restrict__ esrc4,
                const int4* __restrict__ edst4,
                const int4* __restrict__ elab4)
{
    int t = blockIdx.x * blockDim.x + threadIdx.x;
    if (t >= N_EDGES / 4) return;
    int4 s = __ldg(&esrc4[t]);
    int4 d = __ldg(&edst4[t]);
    int4 l = __ldg(&elab4[t]);

    unsigned w0 = ((unsigned)g_lbl8[s.x] * L + g_lbl8[d.x]) * EL + (unsigned)l.x + 1u;
    unsigned w1 = ((unsigned)g_lbl8[s.y] * L + g_lbl8[d.y]) * EL + (unsigned)l.y + 1u;
    unsigned w2 = ((unsigned)g_lbl8[s.z] * L + g_lbl8[d.z]) * EL + (unsigned)l.z + 1u;
    unsigned w3 = ((unsigned)g_lbl8[s.w] * L + g_lbl8[d.w]) * EL + (unsigned)l.w + 1u;

    int p0 = atomicAdd(&g_cnt[d.x], 1);
    int p1 = atomicAdd(&g_cnt[d.y], 1);
    int p2 = atomicAdd(&g_cnt[d.z], 1);
    int p3 = atomicAdd(&g_cnt[d.w], 1);

    g_edata[(size_t)d.x * CAP + p0] = (unsigned)s.x | (w0 << 17);
    g_edata[(size_t)d.y * CAP + p1] = (unsigned)s.y | (w1 << 17);
    g_edata[(size_t)d.z * CAP + p2] = (unsigned)s.z | (w2 << 17);
    g_edata[(size_t)d.w * CAP + p3] = (unsigned)s.w | (w3 << 17);
}

// ---------------------------------------------------------------------------
// Node accumulation: 8 edges per iteration, lane = 8*g + c.
// Group g handles edges (j+2g, j+2g+1): one LDG.64 fetches both records.
// fp32 feature rows: one LDG.128 per edge per lane, zero unpack ALU.
// No tail predication: padded slots have weight-index 0 -> Wp[0] = 0.
// ---------------------------------------------------------------------------
__device__ __forceinline__
float4 node_acc(const float* __restrict__ x_in,
                const float* __restrict__ Wp,
                const unsigned* __restrict__ edata,
                int cnt, int g, int c)
{
    const char* xb = (const char*)x_in + c * 16;     // per-lane 4-float chunk base
    const uint2* ed2 = reinterpret_cast<const uint2*>(edata);
    float4 acc = make_float4(0.f, 0.f, 0.f, 0.f);
    int cnt_r = (cnt + 7) & ~7;
    #pragma unroll 2
    for (int j = 0; j < cnt_r; j += 8) {
        uint2 rr = __ldg(&ed2[(j >> 1) + g]);        // records j+2g, j+2g+1
        float w0 = __ldg(&Wp[rr.x >> 17]);
        float w1 = __ldg(&Wp[rr.y >> 17]);
        float4 a0 = __ldg(reinterpret_cast<const float4*>(xb + (size_t)(rr.x & 0x1FFFFu) * 128u));
        float4 a1 = __ldg(reinterpret_cast<const float4*>(xb + (size_t)(rr.y & 0x1FFFFu) * 128u));
        acc.x = fmaf(w0, a0.x, acc.x);
        acc.y = fmaf(w0, a0.y, acc.y);
        acc.z = fmaf(w0, a0.z, acc.z);
        acc.w = fmaf(w0, a0.w, acc.w);
        acc.x = fmaf(w1, a1.x, acc.x);
        acc.y = fmaf(w1, a1.y, acc.y);
        acc.z = fmaf(w1, a1.z, acc.z);
        acc.w = fmaf(w1, a1.w, acc.w);
    }
    return acc;
}

__device__ __forceinline__
float4 reduce_groups(float4 a)
{
    #pragma unroll
    for (int m = 8; m <= 16; m <<= 1) {
        a.x += __shfl_xor_sync(0xffffffffu, a.x, m);
        a.y += __shfl_xor_sync(0xffffffffu, a.y, m);
        a.z += __shfl_xor_sync(0xffffffffu, a.z, m);
        a.w += __shfl_xor_sync(0xffffffffu, a.w, m);
    }
    return a;
}

// ---------------------------------------------------------------------------
// conv layers 1,2
// ---------------------------------------------------------------------------
__global__ __launch_bounds__(256)
void conv_ell(const float* __restrict__ x_in,
              float*       __restrict__ h_out,
              const float* __restrict__ Wp,
              const float* __restrict__ b)
{
    int n    = (blockIdx.x * blockDim.x + threadIdx.x) >> 5;
    int lane = threadIdx.x & 31;
    if (n >= N_NODES) return;
    int g = lane >> 3, c = lane & 7;

    int cnt = __ldg(&g_cnt[n]);
    float4 acc = node_acc(x_in, Wp, &g_edata[(size_t)n * CAP], cnt, g, c);
    acc = reduce_groups(acc);

    if (g == 0) {
        float bias = b[g_lbl8[n]];
        float4 st;
        st.x = tanhf(acc.x + bias);
        st.y = tanhf(acc.y + bias);
        st.z = tanhf(acc.z + bias);
        st.w = tanhf(acc.w + bias);
        reinterpret_cast<float4*>(h_out)[(size_t)n * 8 + c] = st;
    }
}

// ---------------------------------------------------------------------------
// conv layer 3 fused with label pooling
// ---------------------------------------------------------------------------
__global__ __launch_bounds__(256)
void conv_ell_pool(const float* __restrict__ x_in,
                   const float* __restrict__ Wp,
                   const float* __restrict__ b)
{
    __shared__ float pool[L * F];
    for (int i = threadIdx.x; i < L * F; i += blockDim.x) pool[i] = 0.0f;
    __syncthreads();

    int lane = threadIdx.x & 31;
    int g = lane >> 3, c = lane & 7;
    int wpb = blockDim.x >> 5;
    int n0  = blockIdx.x * wpb + (threadIdx.x >> 5);
    int ns  = gridDim.x * wpb;

    for (int n = n0; n < N_NODES; n += ns) {
        int cnt = __ldg(&g_cnt[n]);
        float4 acc = node_acc(x_in, Wp, &g_edata[(size_t)n * CAP], cnt, g, c);
        acc = reduce_groups(acc);
        if (g == 0) {
            int   l    = g_lbl8[n];
            float bias = b[l];
            atomicAdd(&pool[l * F + 4 * c + 0], tanhf(acc.x + bias));
            atomicAdd(&pool[l * F + 4 * c + 1], tanhf(acc.y + bias));
            atomicAdd(&pool[l * F + 4 * c + 2], tanhf(acc.z + bias));
            atomicAdd(&pool[l * F + 4 * c + 3], tanhf(acc.w + bias));
        }
    }
    __syncthreads();

    for (int i = threadIdx.x; i < L * F; i += blockDim.x)
        atomicAdd(&g_sums[i], pool[i]);
}

// ---------------------------------------------------------------------------
__global__ __launch_bounds__(512)
void final_head(const float* __restrict__ Wr,
                const float* __restrict__ br,
                float* __restrict__ out)
{
    __shared__ float red[512];
    int t = threadIdx.x;
    int k = t & 15;
    int chunk = t >> 4;

    float acc = 0.0f;
    for (int i = chunk; i < L * F; i += 32)
        acc += g_sums[i] * Wr[i * K + k];
    red[t] = acc;
    __syncthreads();

    #pragma unroll
    for (int s = 256; s >= 16; s >>= 1) {
        if (t < s) red[t] += red[t + s];
        __syncthreads();
    }
    if (t < K) out[t] = tanhf(red[t] + br[t]);
    __syncthreads();

    for (int i = t; i < L * F; i += 512) g_sums[i] = 0.0f;   // reset invariant
}

// ---------------------------------------------------------------------------
// inputs: 0:x 1:W1 2:b1 3:W2 4:b2 5:W3 6:b3 7:Wr 8:br 9:node_labels
//         10:edge_src 11:edge_dst 12:edge_labels
// ---------------------------------------------------------------------------
extern "C" void kernel_launch(void* const* d_in, const int* in_sizes, int n_in,
                              void* d_out, int out_size)
{
    const float* x   = (const float*)d_in[0];
    const float* W1  = (const float*)d_in[1];
    const float* b1  = (const float*)d_in[2];
    const float* W2  = (const float*)d_in[3];
    const float* b2  = (const float*)d_in[4];
    const float* W3  = (const float*)d_in[5];
    const float* b3  = (const float*)d_in[6];
    const float* Wr  = (const float*)d_in[7];
    const float* br  = (const float*)d_in[8];
    const int* lbl   = (const int*)d_in[9];
    const int* esrc  = (const int*)d_in[10];
    const int* edst  = (const int*)d_in[11];
    const int* elab  = (const int*)d_in[12];
    float* out = (float*)d_out;

    float *hA, *hB, *wp0, *wp1, *wp2;
    cudaGetSymbolAddress((void**)&hA,  g_hA);
    cudaGetSymbolAddress((void**)&hB,  g_hB);
    cudaGetSymbolAddress((void**)&wp0, g_Wp0);
    cudaGetSymbolAddress((void**)&wp1, g_Wp1);
    cudaGetSymbolAddress((void**)&wp2, g_Wp2);

    const int ng = (N_NODES + 255) / 256;            // 391
    const int bg = (N_EDGES / 4 + 255) / 256;        // 3125
    const int cg = (N_NODES * 32 + 255) / 256;       // warp per node

    prep_all<<<ng, 256>>>(lbl, W1, W2, W3);
    build_ell4<<<bg, 256>>>((const int4*)esrc, (const int4*)edst, (const int4*)elab);

    conv_ell<<<cg, 256>>>(x,  hA, wp0, b1);
    conv_ell<<<cg, 256>>>(hA, hB, wp1, b2);
    conv_ell_pool<<<1184, 256>>>(hB, wp2, b3);

    final_head<<<1, 512>>>(Wr, br, out);
}